// round 13
// baseline (speedup 1.0000x reference)
#include <cuda_runtime.h>
#include <cstdint>

// Problem constants
#define B 128
#define T 512
#define I 50
#define H 256
#define K_SMEM 96           // k-range of W kept in shared memory (rnn)
#define K_REG  160          // k-range of W kept in registers (rnn)
#define PITCH 100           // smem pitch in floats (conflict-free LDS.128)
#define IPAD 52

// Scratch: xp[dir][t][b][h]  (fp32), 134 MB
__device__ float g_xp[2u * T * B * H];
// per-8-timestep completion counters: group g done when g_flag8[g] == 8
__device__ int g_flag8[T / 8];

// ---------------------------------------------------------------------------
// packed fp32x2 helpers (Blackwell)
// ---------------------------------------------------------------------------
__device__ __forceinline__ unsigned long long ffma2(unsigned long long a,
                                                    unsigned long long b,
                                                    unsigned long long c) {
    unsigned long long d;
    asm("fma.rn.f32x2 %0, %1, %2, %3;" : "=l"(d) : "l"(a), "l"(b), "l"(c));
    return d;
}
__device__ __forceinline__ float2 u2f(unsigned long long v) {
    float2 f;
    asm("mov.b64 {%0, %1}, %2;" : "=f"(f.x), "=f"(f.y) : "l"(v));
    return f;
}
__device__ __forceinline__ unsigned long long f2u(float lo, float hi) {
    unsigned long long v;
    asm("mov.b64 %0, {%1, %2};" : "=l"(v) : "f"(lo), "f"(hi));
    return v;
}
__device__ __forceinline__ float ld_cg(const float* p) {
    float v;
    asm volatile("ld.global.cg.f32 %0, [%1];" : "=f"(v) : "l"(p));
    return v;
}
__device__ __forceinline__ void spin_group(int g) {
    const int* fp = &g_flag8[g];
    int v;
    while (true) {
        asm volatile("ld.acquire.gpu.global.s32 %0, [%1];" : "=r"(v) : "l"(fp));
        if (v >= 8) break;
        __nanosleep(128);
    }
}

// ---------------------------------------------------------------------------
// Producer kernel (np CTAs, own compilation -> free register budget).
// Block w computes xp[fwd][s] AND xp[bwd][s] for s = w, w+np, ...
// Thread: h2 = tid&127 -> neurons {2h2, 2h2+1}, dir = tid>>7.
// Software-pipelined: next task's x loaded into registers during compute.
// ---------------------------------------------------------------------------
__global__ __launch_bounds__(256) void proj_kernel(
    int np,
    const float* __restrict__ x,
    const float* __restrict__ w_ih_f, const float* __restrict__ b_ih_f, const float* __restrict__ b_hh_f,
    const float* __restrict__ w_ih_b, const float* __restrict__ b_ih_b, const float* __restrict__ b_hh_b)
{
    extern __shared__ float xs[];        // [2 buf][2 dir][B][IPAD] = 106,496 B
    const int w   = blockIdx.x;
    const int tid = threadIdx.x;
    const int h2  = tid & 127;
    const int dir = tid >> 7;
    const int lt  = tid & 127;

    const float* wsrc = dir ? w_ih_b : w_ih_f;
    const float* bih  = dir ? b_ih_b : b_ih_f;
    const float* bhh  = dir ? b_hh_b : b_hh_f;
    unsigned long long w0[26], w1[26];
    {
        const float* p0 = wsrc + (size_t)(2 * h2) * I;
        const float* p1 = wsrc + (size_t)(2 * h2 + 1) * I;
        #pragma unroll
        for (int i = 0; i < 25; i++) {
            w0[i] = f2u(p0[2 * i], p0[2 * i + 1]);
            w1[i] = f2u(p1[2 * i], p1[2 * i + 1]);
        }
        w0[25] = 0ull;
        w1[25] = 0ull;
    }
    const float bias0 = bih[2 * h2]     + bhh[2 * h2];
    const float bias1 = bih[2 * h2 + 1] + bhh[2 * h2 + 1];

    // zero both buffers once (covers pad lanes)
    for (int i = tid; i < 2 * 2 * B * IPAD; i += 256) xs[i] = 0.f;
    __syncthreads();

    // prologue: stage task s=w into buffer 0
    {
        const int tsrc = dir ? (T - 1 - w) : w;
        float* xsd = xs + dir * (B * IPAD);
        for (int idx = lt; idx < B * I; idx += 128) {
            int b = idx / I;
            int i = idx - b * I;
            xsd[b * IPAD + i] = x[((size_t)b * T + tsrc) * I + i];
        }
    }
    __syncthreads();

    int pb = 0;
    for (int s = w; s < T; s += np) {
        const int snext = s + np;
        const bool have_next = (snext < T);

        // issue next task's x loads into registers (latency hides under compute)
        float r[50];
        if (have_next) {
            const int tsrc = dir ? (T - 1 - snext) : snext;
            #pragma unroll
            for (int jj = 0; jj < 50; jj++) {
                int idx = lt + jj * 128;         // B*I = 6400 = 50*128 exactly
                int b = idx / I;
                int i = idx - b * I;
                r[jj] = __ldg(&x[((size_t)b * T + tsrc) * I + i]);
            }
        }

        // compute from buffer pb
        const float* xsme = xs + (pb * 2 + dir) * (B * IPAD);
        float* xp_out = g_xp + (((size_t)dir * T + s) * B) * H + 2 * h2;
        #pragma unroll 2
        for (int b = 0; b < B; b++) {
            const ulonglong2* xb = reinterpret_cast<const ulonglong2*>(&xsme[b * IPAD]);
            unsigned long long a00 = 0ull, a01 = 0ull, a10 = 0ull, a11 = 0ull;
            #pragma unroll
            for (int i = 0; i < 13; i++) {
                ulonglong2 xv = xb[i];
                a00 = ffma2(xv.x, w0[2 * i],     a00);
                a01 = ffma2(xv.y, w0[2 * i + 1], a01);
                a10 = ffma2(xv.x, w1[2 * i],     a10);
                a11 = ffma2(xv.y, w1[2 * i + 1], a11);
            }
            float2 f00 = u2f(a00), f01 = u2f(a01);
            float2 f10 = u2f(a10), f11 = u2f(a11);
            float2 o;
            o.x = bias0 + ((f00.x + f00.y) + (f01.x + f01.y));
            o.y = bias1 + ((f10.x + f10.y) + (f11.x + f11.y));
            *reinterpret_cast<float2*>(xp_out + (size_t)b * H) = o;
        }

        // dump staged registers into the alternate buffer
        if (have_next) {
            float* xsd = xs + ((pb ^ 1) * 2 + dir) * (B * IPAD);
            #pragma unroll
            for (int jj = 0; jj < 50; jj++) {
                int idx = lt + jj * 128;
                int b = idx / I;
                int i = idx - b * I;
                xsd[b * IPAD + i] = r[jj];
            }
        }

        __threadfence();                 // publish xp stores device-wide
        __syncthreads();                 // all threads' stores + staging done
        if (tid == 0) atomicAdd(&g_flag8[s >> 3], 1);
        pb ^= 1;
    }
}

// ---------------------------------------------------------------------------
// Consumer kernel: BYTE-EXACT round-2 recurrence (781 us), with only:
//  - xp loads via ld.global.cg (L2-coherent)
//  - a group-flag wait every 8 steps
// Compiled standalone -> regs ~242, sacred schedule preserved.
// ---------------------------------------------------------------------------
__global__ __launch_bounds__(256, 1) void rnn_kernel(
    const float* __restrict__ w_hh_f,
    const float* __restrict__ w_hh_b,
    float* __restrict__ out)
{
    extern __shared__ float sm[];
    float* Wsh = sm;                       // [256][PITCH]
    float* hs  = sm + 256 * PITCH;         // [2 buf][2 rows][256]

    const int dir = blockIdx.x >> 6;
    const int j   = blockIdx.x & 63;
    const int b0  = 2 * j;
    const int t   = threadIdx.x;

    const float* __restrict__ W = dir ? w_hh_b : w_hh_f;

    for (int idx = t; idx < 256 * K_SMEM; idx += 256) {
        int n = idx / K_SMEM;
        int k = idx - n * K_SMEM;
        Wsh[n * PITCH + k] = W[n * H + k];
    }
    ulonglong2 wreg[K_REG / 4];
    {
        const ulonglong2* wrow = reinterpret_cast<const ulonglong2*>(W + (size_t)t * H + K_SMEM);
        #pragma unroll
        for (int r = 0; r < K_REG / 4; r++) wreg[r] = wrow[r];
    }
    hs[0 * 512 + 0 * 256 + t] = 0.f;
    hs[0 * 512 + 1 * 256 + t] = 0.f;
    __syncthreads();

    const float* xp0 = g_xp + ((size_t)dir * T * B + b0) * H + t;
    const float* xp1 = xp0 + H;
    const size_t step_stride = (size_t)B * H;

    spin_group(0);
    float xa = ld_cg(xp0);
    float xb = ld_cg(xp1);

    float* out_t = out + (size_t)dir * H + t;

    int buf = 0;
    for (int s = 0; s < T; s++) {
        if ((s & 7) == 0 && s < T - 8) spin_group((s >> 3) + 1);

        float nxa = 0.f, nxb = 0.f;
        if (s < T - 1) {
            nxa = ld_cg(xp0 + (size_t)(s + 1) * step_stride);
            nxb = ld_cg(xp1 + (size_t)(s + 1) * step_stride);
        }

        const ulonglong2* h0v = reinterpret_cast<const ulonglong2*>(hs + buf * 512);
        const ulonglong2* h1v = reinterpret_cast<const ulonglong2*>(hs + buf * 512 + 256);
        const ulonglong2* wv  = reinterpret_cast<const ulonglong2*>(Wsh + t * PITCH);

        unsigned long long aA0 = 0ull, aB0 = 0ull, aA1 = 0ull, aB1 = 0ull;

        #pragma unroll
        for (int i = 0; i < K_SMEM / 4; i++) {
            ulonglong2 w  = wv[i];
            ulonglong2 ha = h0v[i];
            ulonglong2 hb = h1v[i];
            aA0 = ffma2(w.x, ha.x, aA0);
            aB0 = ffma2(w.y, ha.y, aB0);
            aA1 = ffma2(w.x, hb.x, aA1);
            aB1 = ffma2(w.y, hb.y, aB1);
        }
        #pragma unroll
        for (int r = 0; r < K_REG / 4; r++) {
            ulonglong2 w  = wreg[r];
            ulonglong2 ha = h0v[K_SMEM / 4 + r];
            ulonglong2 hb = h1v[K_SMEM / 4 + r];
            aA0 = ffma2(w.x, ha.x, aA0);
            aB0 = ffma2(w.y, ha.y, aB0);
            aA1 = ffma2(w.x, hb.x, aA1);
            aB1 = ffma2(w.y, hb.y, aB1);
        }

        float2 fA0 = u2f(aA0), fB0 = u2f(aB0);
        float2 fA1 = u2f(aA1), fB1 = u2f(aB1);
        float h0 = fmaxf(xa + ((fA0.x + fA0.y) + (fB0.x + fB0.y)), 0.f);
        float h1 = fmaxf(xb + ((fA1.x + fA1.y) + (fB1.x + fB1.y)), 0.f);

        const int time = dir ? (T - 1 - s) : s;
        out_t[((size_t)b0 * T + time) * (2 * H)] = h0;
        out_t[((size_t)(b0 + 1) * T + time) * (2 * H)] = h1;

        const int nb = buf ^ 1;
        hs[nb * 512 + t]       = h0;
        hs[nb * 512 + 256 + t] = h1;
        __syncthreads();

        buf = nb;
        xa = nxa;
        xb = nxb;
    }
}

// ---------------------------------------------------------------------------
// Launch: memset flags -> fork side stream -> proj (side) || rnn (main) -> join.
// Both kernels are independent graph nodes and execute concurrently; the 128
// rnn CTAs (1/SM, reg-limited) leave (SMs-128) SMs for the proj CTAs.
// ---------------------------------------------------------------------------
extern "C" void kernel_launch(void* const* d_in, const int* in_sizes, int n_in,
                              void* d_out, int out_size)
{
    const float* x      = (const float*)d_in[0];
    const float* w_ih_f = (const float*)d_in[1];
    const float* w_hh_f = (const float*)d_in[2];
    const float* b_ih_f = (const float*)d_in[3];
    const float* b_hh_f = (const float*)d_in[4];
    const float* w_ih_b = (const float*)d_in[5];
    const float* w_hh_b = (const float*)d_in[6];
    const float* b_ih_b = (const float*)d_in[7];
    const float* b_hh_b = (const float*)d_in[8];
    float* out = (float*)d_out;

    static int nprod = -1;
    static void* flag_addr = nullptr;
    static cudaStream_t side = nullptr;
    static cudaEvent_t ev_fork = nullptr, ev_join = nullptr;
    const int rnn_smem  = 256 * PITCH * 4 + 2 * 2 * 256 * 4;   // 106,496 B
    const int proj_smem = 2 * 2 * B * IPAD * 4;                // 106,496 B
    if (nprod < 0) {
        cudaFuncSetAttribute(rnn_kernel,  cudaFuncAttributeMaxDynamicSharedMemorySize, rnn_smem);
        cudaFuncSetAttribute(proj_kernel, cudaFuncAttributeMaxDynamicSharedMemorySize, proj_smem);
        cudaGetSymbolAddress(&flag_addr, g_flag8);
        cudaStreamCreateWithFlags(&side, cudaStreamNonBlocking);
        cudaEventCreateWithFlags(&ev_fork, cudaEventDisableTiming);
        cudaEventCreateWithFlags(&ev_join, cudaEventDisableTiming);
        int dev = 0, sms = 148;
        cudaGetDevice(&dev);
        cudaDeviceGetAttribute(&sms, cudaDevAttrMultiProcessorCount, dev);
        nprod = sms - 128;
        if (nprod < 12) nprod = 12;
        if (nprod > 24) nprod = 24;
    }

    // zero the pipeline flags (main stream), then fork
    cudaMemsetAsync(flag_addr, 0, sizeof(int) * (T / 8));
    cudaEventRecord(ev_fork, 0);
    cudaStreamWaitEvent(side, ev_fork, 0);

    // producer on side stream (concurrent with consumer)
    proj_kernel<<<nprod, 256, proj_smem, side>>>(
        nprod, x, w_ih_f, b_ih_f, b_hh_f, w_ih_b, b_ih_b, b_hh_b);
    cudaEventRecord(ev_join, side);

    // consumer on main stream
    rnn_kernel<<<128, 256, rnn_smem>>>(w_hh_f, w_hh_b, out);

    // join side stream back into main
    cudaStreamWaitEvent(0, ev_join, 0);
}

// round 14
// speedup vs baseline: 1.0329x; 1.0329x over previous
#include <cuda_runtime.h>
#include <cstdint>

// Problem constants
#define B 128
#define T 512
#define I 50
#define H 256
#define K_SMEM 96           // k-range of W kept in shared memory (rnn role)
#define K_REG  160          // k-range of W kept in registers (rnn role)
#define PITCH 100           // smem pitch in floats (conflict-free LDS.128)
#define IPAD 52

// Scratch: xp[dir][t][b][h]  (fp32), 134 MB
__device__ float g_xp[2u * T * B * H];
// per-8-timestep completion counters: group g done when g_flag8[g] == 8
__device__ int g_flag8[T / 8];

// ---------------------------------------------------------------------------
// packed fp32x2 helpers (Blackwell)
// ---------------------------------------------------------------------------
__device__ __forceinline__ unsigned long long ffma2(unsigned long long a,
                                                    unsigned long long b,
                                                    unsigned long long c) {
    unsigned long long d;
    asm("fma.rn.f32x2 %0, %1, %2, %3;" : "=l"(d) : "l"(a), "l"(b), "l"(c));
    return d;
}
__device__ __forceinline__ float2 u2f(unsigned long long v) {
    float2 f;
    asm("mov.b64 {%0, %1}, %2;" : "=f"(f.x), "=f"(f.y) : "l"(v));
    return f;
}
__device__ __forceinline__ unsigned long long f2u(float lo, float hi) {
    unsigned long long v;
    asm("mov.b64 %0, {%1, %2};" : "=l"(v) : "f"(lo), "f"(hi));
    return v;
}
__device__ __forceinline__ float ld_cg(const float* p) {
    float v;
    asm volatile("ld.global.cg.f32 %0, [%1];" : "=f"(v) : "l"(p));
    return v;
}
__device__ __forceinline__ void spin_group(int g) {
    const int* fp = &g_flag8[g];
    int v;
    while (true) {
        asm volatile("ld.acquire.gpu.global.s32 %0, [%1];" : "=r"(v) : "l"(fp));
        if (v >= 8) break;
        __nanosleep(128);
    }
}

// ---------------------------------------------------------------------------
// Producer role (blocks 0..np-1, np = gridDim.x - 128): block w computes
// xp[fwd][s] AND xp[bwd][s] for s = w, w+np, ...
// Thread: h2 = tid&127 -> neurons {2h2, 2h2+1}, dir = tid>>7.
// IDENTICAL structure to round-11's producer (regs stayed at 242 then).
// ---------------------------------------------------------------------------
__device__ __forceinline__ void proj_role(
    int w, int np, int tid, float* xs,
    const float* __restrict__ x,
    const float* __restrict__ w_ih_f, const float* __restrict__ b_ih_f, const float* __restrict__ b_hh_f,
    const float* __restrict__ w_ih_b, const float* __restrict__ b_ih_b, const float* __restrict__ b_hh_b)
{
    const int h2  = tid & 127;
    const int dir = tid >> 7;
    const int lt  = tid & 127;       // lane within direction half

    // weight rows (this thread's direction), packed pairs, zero-padded
    const float* wsrc = dir ? w_ih_b : w_ih_f;
    const float* bih  = dir ? b_ih_b : b_ih_f;
    const float* bhh  = dir ? b_hh_b : b_hh_f;
    unsigned long long w0[26], w1[26];
    {
        const float* p0 = wsrc + (size_t)(2 * h2) * I;
        const float* p1 = wsrc + (size_t)(2 * h2 + 1) * I;
        #pragma unroll
        for (int i = 0; i < 25; i++) {
            w0[i] = f2u(p0[2 * i], p0[2 * i + 1]);
            w1[i] = f2u(p1[2 * i], p1[2 * i + 1]);
        }
        w0[25] = 0ull;
        w1[25] = 0ull;
    }
    const float bias0 = bih[2 * h2]     + bhh[2 * h2];
    const float bias1 = bih[2 * h2 + 1] + bhh[2 * h2 + 1];

    // zero the two staging buffers once (covers pad lanes)
    for (int i = tid; i < 2 * B * IPAD; i += 256) xs[i] = 0.f;
    __syncthreads();

    for (int s = w; s < T; s += np) {
        // dir-half d stages x[:, tsrc_d, :] into xs[d]
        const int tsrc = dir ? (T - 1 - s) : s;
        float* xsd = xs + dir * (B * IPAD);
        for (int idx = lt; idx < B * I; idx += 128) {
            int b = idx / I;
            int i = idx - b * I;
            xsd[b * IPAD + i] = x[((size_t)b * T + tsrc) * I + i];
        }
        __syncthreads();

        float* xp_out = g_xp + (((size_t)dir * T + s) * B) * H + 2 * h2;
        const float* xsme = xs + dir * (B * IPAD);
        #pragma unroll 2
        for (int b = 0; b < B; b++) {
            const ulonglong2* xb = reinterpret_cast<const ulonglong2*>(&xsme[b * IPAD]);
            unsigned long long a00 = 0ull, a01 = 0ull, a10 = 0ull, a11 = 0ull;
            #pragma unroll
            for (int i = 0; i < 13; i++) {
                ulonglong2 xv = xb[i];
                a00 = ffma2(xv.x, w0[2 * i],     a00);
                a01 = ffma2(xv.y, w0[2 * i + 1], a01);
                a10 = ffma2(xv.x, w1[2 * i],     a10);
                a11 = ffma2(xv.y, w1[2 * i + 1], a11);
            }
            float2 f00 = u2f(a00), f01 = u2f(a01);
            float2 f10 = u2f(a10), f11 = u2f(a11);
            float2 o;
            o.x = bias0 + ((f00.x + f00.y) + (f01.x + f01.y));
            o.y = bias1 + ((f10.x + f10.y) + (f11.x + f11.y));
            *reinterpret_cast<float2*>(xp_out + (size_t)b * H) = o;
        }

        __syncthreads();                 // all stores of this task issued
        if (tid == 0) {
            __threadfence();             // publish xp before flag
            atomicAdd(&g_flag8[s >> 3], 1);
        }
    }
}

// ---------------------------------------------------------------------------
// Consumer role: BYTE-EXACT round-2 recurrence loop (781 us), with only:
//  - xp loads via ld.global.cg (L2-coherent)
//  - a group-flag wait every 8 steps (rarely-taken branch)
// DO NOT otherwise modify (R7/R9: any reorder regresses 15-25%).
// ---------------------------------------------------------------------------
__device__ __forceinline__ void rnn_role(
    int bi, int t, float* sm,
    const float* __restrict__ w_hh_f,
    const float* __restrict__ w_hh_b,
    float* __restrict__ out)
{
    float* Wsh = sm;                       // [256][PITCH]
    float* hs  = sm + 256 * PITCH;         // [2 buf][2 rows][256]

    const int dir = bi >> 6;
    const int j   = bi & 63;
    const int b0  = 2 * j;

    const float* __restrict__ W = dir ? w_hh_b : w_hh_f;

    // W[:, 0:K_SMEM] -> smem
    for (int idx = t; idx < 256 * K_SMEM; idx += 256) {
        int n = idx / K_SMEM;
        int k = idx - n * K_SMEM;
        Wsh[n * PITCH + k] = W[n * H + k];
    }
    // W[t, K_SMEM:256] -> regs, as packed (k,k+1) pairs
    ulonglong2 wreg[K_REG / 4];
    {
        const ulonglong2* wrow = reinterpret_cast<const ulonglong2*>(W + (size_t)t * H + K_SMEM);
        #pragma unroll
        for (int r = 0; r < K_REG / 4; r++) wreg[r] = wrow[r];
    }
    hs[0 * 512 + 0 * 256 + t] = 0.f;
    hs[0 * 512 + 1 * 256 + t] = 0.f;
    __syncthreads();

    const float* xp0 = g_xp + ((size_t)dir * T * B + b0) * H + t;
    const float* xp1 = xp0 + H;
    const size_t step_stride = (size_t)B * H;

    spin_group(0);                         // timesteps 0..7 ready
    float xa = ld_cg(xp0);
    float xb = ld_cg(xp1);

    float* out_t = out + (size_t)dir * H + t;

    int buf = 0;
    for (int s = 0; s < T; s++) {
        if ((s & 7) == 0 && s < T - 8) spin_group((s >> 3) + 1);

        float nxa = 0.f, nxb = 0.f;
        if (s < T - 1) {
            nxa = ld_cg(xp0 + (size_t)(s + 1) * step_stride);
            nxb = ld_cg(xp1 + (size_t)(s + 1) * step_stride);
        }

        const ulonglong2* h0v = reinterpret_cast<const ulonglong2*>(hs + buf * 512);
        const ulonglong2* h1v = reinterpret_cast<const ulonglong2*>(hs + buf * 512 + 256);
        const ulonglong2* wv  = reinterpret_cast<const ulonglong2*>(Wsh + t * PITCH);

        unsigned long long aA0 = 0ull, aB0 = 0ull, aA1 = 0ull, aB1 = 0ull;

        #pragma unroll
        for (int i = 0; i < K_SMEM / 4; i++) {
            ulonglong2 w  = wv[i];
            ulonglong2 ha = h0v[i];
            ulonglong2 hb = h1v[i];
            aA0 = ffma2(w.x, ha.x, aA0);
            aB0 = ffma2(w.y, ha.y, aB0);
            aA1 = ffma2(w.x, hb.x, aA1);
            aB1 = ffma2(w.y, hb.y, aB1);
        }
        #pragma unroll
        for (int r = 0; r < K_REG / 4; r++) {
            ulonglong2 w  = wreg[r];
            ulonglong2 ha = h0v[K_SMEM / 4 + r];
            ulonglong2 hb = h1v[K_SMEM / 4 + r];
            aA0 = ffma2(w.x, ha.x, aA0);
            aB0 = ffma2(w.y, ha.y, aB0);
            aA1 = ffma2(w.x, hb.x, aA1);
            aB1 = ffma2(w.y, hb.y, aB1);
        }

        float2 fA0 = u2f(aA0), fB0 = u2f(aB0);
        float2 fA1 = u2f(aA1), fB1 = u2f(aB1);
        float h0 = fmaxf(xa + ((fA0.x + fA0.y) + (fB0.x + fB0.y)), 0.f);
        float h1 = fmaxf(xb + ((fA1.x + fA1.y) + (fB1.x + fB1.y)), 0.f);

        const int time = dir ? (T - 1 - s) : s;
        out_t[((size_t)b0 * T + time) * (2 * H)] = h0;
        out_t[((size_t)(b0 + 1) * T + time) * (2 * H)] = h1;

        const int nb = buf ^ 1;
        hs[nb * 512 + t]       = h0;
        hs[nb * 512 + 256 + t] = h1;
        __syncthreads();

        buf = nb;
        xa = nxa;
        xb = nxb;
    }
}

// ---------------------------------------------------------------------------
// Fused kernel: blocks 0..np-1 produce xp (np = gridDim.x - 128), blocks
// np..gridDim.x-1 run the recurrence. Grid <= SM count -> co-resident.
// Same signature as round 11 (np derived from gridDim, not an argument).
// ---------------------------------------------------------------------------
__global__ __launch_bounds__(256, 1) void fused_kernel(
    const float* __restrict__ x,
    const float* __restrict__ w_ih_f, const float* __restrict__ b_ih_f, const float* __restrict__ b_hh_f,
    const float* __restrict__ w_ih_b, const float* __restrict__ b_ih_b, const float* __restrict__ b_hh_b,
    const float* __restrict__ w_hh_f, const float* __restrict__ w_hh_b,
    float* __restrict__ out)
{
    extern __shared__ float sm[];
    const int np  = (int)gridDim.x - 128;
    const int bi  = blockIdx.x;
    const int tid = threadIdx.x;

    if (bi < np) {
        proj_role(bi, np, tid, sm, x, w_ih_f, b_ih_f, b_hh_f, w_ih_b, b_ih_b, b_hh_b);
    } else {
        rnn_role(bi - np, tid, sm, w_hh_f, w_hh_b, out);
    }
}

// ---------------------------------------------------------------------------
extern "C" void kernel_launch(void* const* d_in, const int* in_sizes, int n_in,
                              void* d_out, int out_size)
{
    const float* x      = (const float*)d_in[0];
    const float* w_ih_f = (const float*)d_in[1];
    const float* w_hh_f = (const float*)d_in[2];
    const float* b_ih_f = (const float*)d_in[3];
    const float* b_hh_f = (const float*)d_in[4];
    const float* w_ih_b = (const float*)d_in[5];
    const float* w_hh_b = (const float*)d_in[6];
    const float* b_ih_b = (const float*)d_in[7];
    const float* b_hh_b = (const float*)d_in[8];
    float* out = (float*)d_out;

    static int nprod = -1;
    static void* flag_addr = nullptr;
    const int smem_bytes = 256 * PITCH * 4 + 2 * 2 * 256 * 4;  // 106,496 B
    if (nprod < 0) {
        cudaFuncSetAttribute(fused_kernel, cudaFuncAttributeMaxDynamicSharedMemorySize, smem_bytes);
        cudaGetSymbolAddress(&flag_addr, g_flag8);
        int dev = 0, sms = 148;
        cudaGetDevice(&dev);
        cudaDeviceGetAttribute(&sms, cudaDevAttrMultiProcessorCount, dev);
        nprod = sms - 128;          // 24 on GB300 (152 SMs), 20 on B300 (148)
        if (nprod < 12) nprod = 12;
        if (nprod > 24) nprod = 24;
    }

    // zero the pipeline flags (graph-capturable memset node)
    cudaMemsetAsync(flag_addr, 0, sizeof(int) * (T / 8));

    // one fused launch: nprod producer CTAs + 128 recurrence CTAs
    fused_kernel<<<nprod + 128, 256, smem_bytes>>>(
        x, w_ih_f, b_ih_f, b_hh_f, w_ih_b, b_ih_b, b_hh_b, w_hh_f, w_hh_b, out);
}

// round 15
// speedup vs baseline: 1.0513x; 1.0178x over previous
#include <cuda_runtime.h>
#include <cstdint>

// Problem constants
#define B 128
#define T 512
#define I 50
#define H 256
#define K_SMEM 96           // k-range of W kept in shared memory (rnn role)
#define K_REG  160          // k-range of W kept in registers (rnn role)
#define PITCH 100           // smem pitch in floats (conflict-free LDS.128)
#define IPAD 52
#define BH 64               // producer task batch-half size

// Scratch: xp[dir][t][b][h]  (fp32), 134 MB
__device__ float g_xp[2u * T * B * H];
// per-8-timestep completion counters: group g done when g_flag8[g] == 16
// (8 timesteps x 2 batch halves)
__device__ int g_flag8[T / 8];

// ---------------------------------------------------------------------------
// packed fp32x2 helpers (Blackwell)
// ---------------------------------------------------------------------------
__device__ __forceinline__ unsigned long long ffma2(unsigned long long a,
                                                    unsigned long long b,
                                                    unsigned long long c) {
    unsigned long long d;
    asm("fma.rn.f32x2 %0, %1, %2, %3;" : "=l"(d) : "l"(a), "l"(b), "l"(c));
    return d;
}
__device__ __forceinline__ float2 u2f(unsigned long long v) {
    float2 f;
    asm("mov.b64 {%0, %1}, %2;" : "=f"(f.x), "=f"(f.y) : "l"(v));
    return f;
}
__device__ __forceinline__ unsigned long long f2u(float lo, float hi) {
    unsigned long long v;
    asm("mov.b64 %0, {%1, %2};" : "=l"(v) : "f"(lo), "f"(hi));
    return v;
}
__device__ __forceinline__ float ld_cg(const float* p) {
    float v;
    asm volatile("ld.global.cg.f32 %0, [%1];" : "=f"(v) : "l"(p));
    return v;
}
__device__ __forceinline__ void spin_group(int g) {
    const int* fp = &g_flag8[g];
    int v;
    while (true) {
        asm volatile("ld.acquire.gpu.global.s32 %0, [%1];" : "=r"(v) : "l"(fp));
        if (v >= 16) break;
        __nanosleep(128);
    }
}

// ---------------------------------------------------------------------------
// Producer role (blocks 0..np-1, np = gridDim.x - 128).
// Task = (timestep s, batch half) -> 2T tasks of ~16us each; block w handles
// task idx = w, w+np, ...  Thread: h2 = tid&127 -> neurons {2h2, 2h2+1},
// dir = tid>>7. Group flag counts to 16 (8 steps x 2 halves).
// Small tasks halve the pipeline fill time vs full-batch tasks.
// ---------------------------------------------------------------------------
__device__ __forceinline__ void proj_role(
    int w, int np, int tid, float* xs,
    const float* __restrict__ x,
    const float* __restrict__ w_ih_f, const float* __restrict__ b_ih_f, const float* __restrict__ b_hh_f,
    const float* __restrict__ w_ih_b, const float* __restrict__ b_ih_b, const float* __restrict__ b_hh_b)
{
    const int h2  = tid & 127;
    const int dir = tid >> 7;
    const int lt  = tid & 127;       // lane within direction half

    // weight rows (this thread's direction), packed pairs, zero-padded
    const float* wsrc = dir ? w_ih_b : w_ih_f;
    const float* bih  = dir ? b_ih_b : b_ih_f;
    const float* bhh  = dir ? b_hh_b : b_hh_f;
    unsigned long long w0[26], w1[26];
    {
        const float* p0 = wsrc + (size_t)(2 * h2) * I;
        const float* p1 = wsrc + (size_t)(2 * h2 + 1) * I;
        #pragma unroll
        for (int i = 0; i < 25; i++) {
            w0[i] = f2u(p0[2 * i], p0[2 * i + 1]);
            w1[i] = f2u(p1[2 * i], p1[2 * i + 1]);
        }
        w0[25] = 0ull;
        w1[25] = 0ull;
    }
    const float bias0 = bih[2 * h2]     + bhh[2 * h2];
    const float bias1 = bih[2 * h2 + 1] + bhh[2 * h2 + 1];

    // zero the staging buffers once (covers pad lanes)
    for (int i = tid; i < 2 * BH * IPAD; i += 256) xs[i] = 0.f;
    __syncthreads();

    for (int idx = w; idx < 2 * T; idx += np) {
        const int s     = idx >> 1;
        const int bbase = (idx & 1) * BH;

        // dir-half stages x[bbase:bbase+BH, tsrc, :] into xs[dir]
        const int tsrc = dir ? (T - 1 - s) : s;
        float* xsd = xs + dir * (BH * IPAD);
        for (int e = lt; e < BH * I; e += 128) {
            int b = e / I;
            int i = e - b * I;
            xsd[b * IPAD + i] = x[((size_t)(bbase + b) * T + tsrc) * I + i];
        }
        __syncthreads();

        float* xp_out = g_xp + (((size_t)dir * T + s) * B + bbase) * H + 2 * h2;
        const float* xsme = xs + dir * (BH * IPAD);
        #pragma unroll 2
        for (int b = 0; b < BH; b++) {
            const ulonglong2* xb = reinterpret_cast<const ulonglong2*>(&xsme[b * IPAD]);
            unsigned long long a00 = 0ull, a01 = 0ull, a10 = 0ull, a11 = 0ull;
            #pragma unroll
            for (int i = 0; i < 13; i++) {
                ulonglong2 xv = xb[i];
                a00 = ffma2(xv.x, w0[2 * i],     a00);
                a01 = ffma2(xv.y, w0[2 * i + 1], a01);
                a10 = ffma2(xv.x, w1[2 * i],     a10);
                a11 = ffma2(xv.y, w1[2 * i + 1], a11);
            }
            float2 f00 = u2f(a00), f01 = u2f(a01);
            float2 f10 = u2f(a10), f11 = u2f(a11);
            float2 o;
            o.x = bias0 + ((f00.x + f00.y) + (f01.x + f01.y));
            o.y = bias1 + ((f10.x + f10.y) + (f11.x + f11.y));
            *reinterpret_cast<float2*>(xp_out + (size_t)b * H) = o;
        }

        __syncthreads();                 // all stores of this task issued
        if (tid == 0) {
            __threadfence();             // publish xp before flag
            atomicAdd(&g_flag8[s >> 3], 1);
        }
    }
}

// ---------------------------------------------------------------------------
// Consumer role: BYTE-EXACT round-2 recurrence loop (781 us), with only:
//  - xp loads via ld.global.cg (L2-coherent)
//  - a group-flag wait at s%8==7 (just before the prefetch that needs it,
//    giving producers ~7 steps more slack than the old s%8==0 check)
// DO NOT otherwise modify (R7/R9: any reorder regresses 15-25%).
// ---------------------------------------------------------------------------
__device__ __forceinline__ void rnn_role(
    int bi, int t, float* sm,
    const float* __restrict__ w_hh_f,
    const float* __restrict__ w_hh_b,
    float* __restrict__ out)
{
    float* Wsh = sm;                       // [256][PITCH]
    float* hs  = sm + 256 * PITCH;         // [2 buf][2 rows][256]

    const int dir = bi >> 6;
    const int j   = bi & 63;
    const int b0  = 2 * j;

    const float* __restrict__ W = dir ? w_hh_b : w_hh_f;

    // W[:, 0:K_SMEM] -> smem
    for (int idx = t; idx < 256 * K_SMEM; idx += 256) {
        int n = idx / K_SMEM;
        int k = idx - n * K_SMEM;
        Wsh[n * PITCH + k] = W[n * H + k];
    }
    // W[t, K_SMEM:256] -> regs, as packed (k,k+1) pairs
    ulonglong2 wreg[K_REG / 4];
    {
        const ulonglong2* wrow = reinterpret_cast<const ulonglong2*>(W + (size_t)t * H + K_SMEM);
        #pragma unroll
        for (int r = 0; r < K_REG / 4; r++) wreg[r] = wrow[r];
    }
    hs[0 * 512 + 0 * 256 + t] = 0.f;
    hs[0 * 512 + 1 * 256 + t] = 0.f;
    __syncthreads();

    const float* xp0 = g_xp + ((size_t)dir * T * B + b0) * H + t;
    const float* xp1 = xp0 + H;
    const size_t step_stride = (size_t)B * H;

    spin_group(0);                         // timesteps 0..7 ready
    float xa = ld_cg(xp0);
    float xb = ld_cg(xp1);

    float* out_t = out + (size_t)dir * H + t;

    int buf = 0;
    for (int s = 0; s < T; s++) {
        // prefetch of xp[s+1] below needs group (s+1)>>3; new group boundary
        // is crossed exactly when s%8==7.
        if ((s & 7) == 7 && s < T - 1) spin_group((s + 1) >> 3);

        float nxa = 0.f, nxb = 0.f;
        if (s < T - 1) {
            nxa = ld_cg(xp0 + (size_t)(s + 1) * step_stride);
            nxb = ld_cg(xp1 + (size_t)(s + 1) * step_stride);
        }

        const ulonglong2* h0v = reinterpret_cast<const ulonglong2*>(hs + buf * 512);
        const ulonglong2* h1v = reinterpret_cast<const ulonglong2*>(hs + buf * 512 + 256);
        const ulonglong2* wv  = reinterpret_cast<const ulonglong2*>(Wsh + t * PITCH);

        unsigned long long aA0 = 0ull, aB0 = 0ull, aA1 = 0ull, aB1 = 0ull;

        #pragma unroll
        for (int i = 0; i < K_SMEM / 4; i++) {
            ulonglong2 w  = wv[i];
            ulonglong2 ha = h0v[i];
            ulonglong2 hb = h1v[i];
            aA0 = ffma2(w.x, ha.x, aA0);
            aB0 = ffma2(w.y, ha.y, aB0);
            aA1 = ffma2(w.x, hb.x, aA1);
            aB1 = ffma2(w.y, hb.y, aB1);
        }
        #pragma unroll
        for (int r = 0; r < K_REG / 4; r++) {
            ulonglong2 w  = wreg[r];
            ulonglong2 ha = h0v[K_SMEM / 4 + r];
            ulonglong2 hb = h1v[K_SMEM / 4 + r];
            aA0 = ffma2(w.x, ha.x, aA0);
            aB0 = ffma2(w.y, ha.y, aB0);
            aA1 = ffma2(w.x, hb.x, aA1);
            aB1 = ffma2(w.y, hb.y, aB1);
        }

        float2 fA0 = u2f(aA0), fB0 = u2f(aB0);
        float2 fA1 = u2f(aA1), fB1 = u2f(aB1);
        float h0 = fmaxf(xa + ((fA0.x + fA0.y) + (fB0.x + fB0.y)), 0.f);
        float h1 = fmaxf(xb + ((fA1.x + fA1.y) + (fB1.x + fB1.y)), 0.f);

        const int time = dir ? (T - 1 - s) : s;
        out_t[((size_t)b0 * T + time) * (2 * H)] = h0;
        out_t[((size_t)(b0 + 1) * T + time) * (2 * H)] = h1;

        const int nb = buf ^ 1;
        hs[nb * 512 + t]       = h0;
        hs[nb * 512 + 256 + t] = h1;
        __syncthreads();

        buf = nb;
        xa = nxa;
        xb = nxb;
    }
}

// ---------------------------------------------------------------------------
// Fused kernel: blocks 0..np-1 produce xp (np = gridDim.x - 128), blocks
// np..gridDim.x-1 run the recurrence. Grid <= SM count -> co-resident.
// ---------------------------------------------------------------------------
__global__ __launch_bounds__(256, 1) void fused_kernel(
    const float* __restrict__ x,
    const float* __restrict__ w_ih_f, const float* __restrict__ b_ih_f, const float* __restrict__ b_hh_f,
    const float* __restrict__ w_ih_b, const float* __restrict__ b_ih_b, const float* __restrict__ b_hh_b,
    const float* __restrict__ w_hh_f, const float* __restrict__ w_hh_b,
    float* __restrict__ out)
{
    extern __shared__ float sm[];
    const int np  = (int)gridDim.x - 128;
    const int bi  = blockIdx.x;
    const int tid = threadIdx.x;

    if (bi < np) {
        proj_role(bi, np, tid, sm, x, w_ih_f, b_ih_f, b_hh_f, w_ih_b, b_ih_b, b_hh_b);
    } else {
        rnn_role(bi - np, tid, sm, w_hh_f, w_hh_b, out);
    }
}

// ---------------------------------------------------------------------------
extern "C" void kernel_launch(void* const* d_in, const int* in_sizes, int n_in,
                              void* d_out, int out_size)
{
    const float* x      = (const float*)d_in[0];
    const float* w_ih_f = (const float*)d_in[1];
    const float* w_hh_f = (const float*)d_in[2];
    const float* b_ih_f = (const float*)d_in[3];
    const float* b_hh_f = (const float*)d_in[4];
    const float* w_ih_b = (const float*)d_in[5];
    const float* w_hh_b = (const float*)d_in[6];
    const float* b_ih_b = (const float*)d_in[7];
    const float* b_hh_b = (const float*)d_in[8];
    float* out = (float*)d_out;

    static int nprod = -1;
    static void* flag_addr = nullptr;
    const int smem_bytes = 256 * PITCH * 4 + 2 * 2 * 256 * 4;  // 106,496 B
    if (nprod < 0) {
        cudaFuncSetAttribute(fused_kernel, cudaFuncAttributeMaxDynamicSharedMemorySize, smem_bytes);
        cudaGetSymbolAddress(&flag_addr, g_flag8);
        int dev = 0, sms = 148;
        cudaGetDevice(&dev);
        cudaDeviceGetAttribute(&sms, cudaDevAttrMultiProcessorCount, dev);
        nprod = sms - 128;          // 24 on GB300 (152 SMs), 20 on B300 (148)
        if (nprod < 12) nprod = 12;
        if (nprod > 24) nprod = 24;
    }

    // zero the pipeline flags (graph-capturable memset node)
    cudaMemsetAsync(flag_addr, 0, sizeof(int) * (T / 8));

    // one fused launch: nprod producer CTAs + 128 recurrence CTAs
    fused_kernel<<<nprod + 128, 256, smem_bytes>>>(
        x, w_ih_f, b_ih_f, b_hh_f, w_ih_b, b_ih_b, b_hh_b, w_hh_f, w_hh_b, out);
}